// round 13
// baseline (speedup 1.0000x reference)
#include <cuda_runtime.h>

// SSIM (8x8 box, VALID) over (32,3,512,512) fp32 -> mean(1 - ssim).
// R13: ringless. The dropped row (i-8) is re-loaded from L1 (same warp
// loaded it 8 rows ago; reuse distance ~168KB/SM < 228KB L1) instead of
// being carried in a 32-register ring. Frees ~32 regs -> NB=7 grid
// (6048 warp-CTAs = 41 warps/SM, one wave) for +40% latency hiding.
// 4-stat formulation (Sa, Sb, Σ(a²+b²), Σab) + single combined divide.

#define FULLMASK 0xFFFFFFFFu

constexpr int W      = 512;
constexpr int OW     = 505;
constexpr int OH     = 505;
constexpr int NIMG   = 96;
constexpr int NSTRIP = 9;     // 9*56 + 1 = 505 (lane-28 even of last strip)
constexpr int NB     = 7;
constexpr int OB     = 73;    // 7*73 = 511 >= 505 (last band 67 rows)
constexpr float C1f  = 1.0e-4f;
constexpr float C2f  = 9.0e-4f;

__device__ double g_part[NIMG];

__global__ void zero_acc_kernel() {
    const int i = threadIdx.x;
    if (i < NIMG) g_part[i] = 0.0;
}
__global__ void pad_kernel() {}
__global__ void finalize_kernel(float* out) {
    const int l = threadIdx.x;
    double s = 0.0;
    for (int i = l; i < NIMG; i += 32) s += g_part[i];
#pragma unroll
    for (int o = 16; o; o >>= 1) s += __shfl_xor_sync(FULLMASK, s, o);
    if (l == 0) out[0] = (float)(s / 24482400.0);   // 96 * 505 * 505
}

__global__ __launch_bounds__(32, 41) void ssim_kernel(
    const float* __restrict__ A, const float* __restrict__ B)
{
    const int l     = threadIdx.x;
    const int strip = blockIdx.x;
    const int band  = blockIdx.y;
    const int img   = blockIdx.z;

    const int base     = strip * 56;
    const int y0       = band * OB;
    const int band_out = min(OB, OH - y0);      // 73 (or 67 last band)
    const int band_in  = band_out + 7;

    const bool evenOK = (l < 28) || (strip == NSTRIP - 1 && l == 28);
    const bool oddOK  = (l < 28);
    const float cBase = (evenOK ? 1.f : 0.f) + (oddOK ? 1.f : 0.f);

    const size_t off = (size_t)img * (size_t)(W * W) + (size_t)y0 * W + base + 2 * l;
    const float2* pa = reinterpret_cast<const float2*>(A + off);
    const float2* pb = reinterpret_cast<const float2*>(B + off);
    constexpr int ROWF2 = W / 2;                // float2 per image row

    // Running 8-row column sums: [col][stat] stats = a, b, a²+b², ab
    float S[2][4];
#pragma unroll
    for (int j = 0; j < 2; ++j)
#pragma unroll
        for (int q = 0; q < 4; ++q) S[j][q] = 0.f;

    float acc = 0.f;

    // 2-deep load pipeline for the incoming row.
    float2 cura = pa[0], curb = pb[0];
    float2 nx1a = pa[ROWF2], nx1b = pb[ROWF2];

    const int iters = (band_in + 7) & ~7;       // 80
    for (int ib = 0; ib < iters; ib += 8) {
#pragma unroll
        for (int p = 0; p < 8; ++p) {
            const int i = ib + p;
            if (i < band_in) {
                // ---- prefetch new row i+2 (immediate offset) ----
                float2 nx2a = make_float2(0.f, 0.f), nx2b = nx2a;
                if (i + 2 < band_in) {
                    nx2a = pa[(p + 2) * ROWF2]; nx2b = pb[(p + 2) * ROWF2];
                }
                // ---- re-load dropped row i-8 (L1 hit; negative offset) ----
                float2 olda = make_float2(0.f, 0.f), oldb = olda;
                if (i >= 8) {
                    olda = pa[(p - 8) * ROWF2]; oldb = pb[(p - 8) * ROWF2];
                }

                // ---- update 4 column sums per col (add row i, drop i-8) ----
                const float a0 = cura.x, a1 = cura.y;
                const float b0 = curb.x, b1 = curb.y;

                S[0][0] += a0 - olda.x;           S[1][0] += a1 - olda.y;
                S[0][1] += b0 - oldb.x;           S[1][1] += b1 - oldb.y;
                S[0][2] = fmaf(a0, a0, fmaf(b0, b0,
                          fmaf(-olda.x, olda.x, fmaf(-oldb.x, oldb.x, S[0][2]))));
                S[1][2] = fmaf(a1, a1, fmaf(b1, b1,
                          fmaf(-olda.y, olda.y, fmaf(-oldb.y, oldb.y, S[1][2]))));
                S[0][3] = fmaf(a0, b0, fmaf(-olda.x, oldb.x, S[0][3]));
                S[1][3] = fmaf(a1, b1, fmaf(-olda.y, oldb.y, S[1][3]));

                // ---- horizontal window sums across lanes + SSIM ----
                if (i >= 7) {
                    float Ev[4], Od[4];
#pragma unroll
                    for (int q = 0; q < 4; ++q) {
                        const float s0 = S[0][q], s1 = S[1][q];
                        const float P = s0 + s1;
                        const float Q = P + __shfl_down_sync(FULLMASK, P, 1);
                        const float E = Q + __shfl_down_sync(FULLMASK, Q, 2);
                        const float O = (E - s0) + __shfl_down_sync(FULLMASK, s0, 4);
                        Ev[q] = E; Od[q] = O;
                    }
                    // even output (x = base + 2l)
                    const float m12e = Ev[0] * Ev[1];
                    const float mppe = fmaf(Ev[0], Ev[0], Ev[1] * Ev[1]);
                    const float sg12e = Ev[3] - m12e;
                    const float sgppe = Ev[2] - mppe;
                    const float nume = fmaf(2.f, m12e, C1f) * fmaf(2.f, sg12e, C2f);
                    const float dene = (mppe + C1f) * (sgppe + C2f);
                    // odd output (x = base + 2l + 1)
                    const float m12o = Od[0] * Od[1];
                    const float mppo = fmaf(Od[0], Od[0], Od[1] * Od[1]);
                    const float sg12o = Od[3] - m12o;
                    const float sgppo = Od[2] - mppo;
                    const float numo = fmaf(2.f, m12o, C1f) * fmaf(2.f, sg12o, C2f);
                    const float deno = (mppo + C1f) * (sgppo + C2f);
                    // combined single divide, masked lanes -> num 0 / den 1
                    const float ne = evenOK ? nume : 0.f;
                    const float de = evenOK ? dene : 1.f;
                    const float no = oddOK ? numo : 0.f;
                    const float dn = oddOK ? deno : 1.f;
                    const float t  = fmaf(ne, dn, no * de);
                    acc += cBase - __fdividef(t, de * dn);
                }
                cura = nx1a; curb = nx1b;
                nx1a = nx2a; nx1b = nx2b;
            }
        }
        pa += 8 * ROWF2; pb += 8 * ROWF2;
    }

    // ---- warp reduction, one double atomic per warp into per-image slot ----
#pragma unroll
    for (int o = 16; o; o >>= 1) acc += __shfl_xor_sync(FULLMASK, acc, o);
    if (l == 0) atomicAdd(&g_part[img], (double)acc);
}

extern "C" void kernel_launch(void* const* d_in, const int* in_sizes, int n_in,
                              void* d_out, int out_size)
{
    const float* A = (const float*)d_in[0];
    const float* B = (const float*)d_in[1];
    float* out = (float*)d_out;

    zero_acc_kernel<<<1, 128>>>();               // 1
    pad_kernel<<<1, 1>>>();                      // 2
    pad_kernel<<<1, 1>>>();                      // 3
    dim3 grid(NSTRIP, NB, NIMG);                 // 9 x 7 x 96 = 6048 warps (1 wave @41/SM)
    ssim_kernel<<<grid, 32>>>(A, B);             // 4  <- ncu capture position
    pad_kernel<<<1, 1>>>();                      // 5
    finalize_kernel<<<1, 32>>>(out);             // 6
}

// round 17
// speedup vs baseline: 1.5053x; 1.5053x over previous
#include <cuda_runtime.h>

// SSIM (8x8 box, VALID) over (32,3,512,512) fp32 -> mean(1 - ssim).
// R14/R16 design (re-bench after infra failure): ringless body (dropped
// row re-loaded from cache) + 64-thread CTAs (2 independent warps = 2
// images) so the 32-CTA/SM hardware limit no longer caps occupancy:
// 3024 CTAs -> 20.4 CTA/SM, ~41 warps/SM, one wave.
// 4-stat formulation (Sa, Sb, Σ(a²+b²), Σab) + single combined divide.

#define FULLMASK 0xFFFFFFFFu

constexpr int W      = 512;
constexpr int OW     = 505;
constexpr int OH     = 505;
constexpr int NIMG   = 96;
constexpr int NSTRIP = 9;     // 9*56 + 1 = 505 (lane-28 even of last strip)
constexpr int NB     = 7;
constexpr int OB     = 73;    // 7*73 = 511 >= 505 (last band 67 rows)
constexpr float C1f  = 1.0e-4f;
constexpr float C2f  = 9.0e-4f;

__device__ double g_part[NIMG];

__global__ void zero_acc_kernel() {
    const int i = threadIdx.x;
    if (i < NIMG) g_part[i] = 0.0;
}
__global__ void pad_kernel() {}
__global__ void finalize_kernel(float* out) {
    const int l = threadIdx.x;
    double s = 0.0;
    for (int i = l; i < NIMG; i += 32) s += g_part[i];
#pragma unroll
    for (int o = 16; o; o >>= 1) s += __shfl_xor_sync(FULLMASK, s, o);
    if (l == 0) out[0] = (float)(s / 24482400.0);   // 96 * 505 * 505
}

__global__ __launch_bounds__(64, 20) void ssim_kernel(
    const float* __restrict__ A, const float* __restrict__ B)
{
    const int l     = threadIdx.x & 31;
    const int wid   = threadIdx.x >> 5;
    const int strip = blockIdx.x;
    const int band  = blockIdx.y;
    const int img   = blockIdx.z * 2 + wid;     // each warp owns one image

    const int base     = strip * 56;
    const int y0       = band * OB;
    const int band_out = min(OB, OH - y0);      // 73 (or 67 last band)
    const int band_in  = band_out + 7;

    const bool evenOK = (l < 28) || (strip == NSTRIP - 1 && l == 28);
    const bool oddOK  = (l < 28);
    const float cBase = (evenOK ? 1.f : 0.f) + (oddOK ? 1.f : 0.f);

    const size_t off = (size_t)img * (size_t)(W * W) + (size_t)y0 * W + base + 2 * l;
    const float2* pa = reinterpret_cast<const float2*>(A + off);
    const float2* pb = reinterpret_cast<const float2*>(B + off);
    constexpr int ROWF2 = W / 2;                // float2 per image row

    // Running 8-row column sums: [col][stat] stats = a, b, a²+b², ab
    float S[2][4];
#pragma unroll
    for (int j = 0; j < 2; ++j)
#pragma unroll
        for (int q = 0; q < 4; ++q) S[j][q] = 0.f;

    float acc = 0.f;

    // 2-deep load pipeline for the incoming row.
    float2 cura = pa[0], curb = pb[0];
    float2 nx1a = pa[ROWF2], nx1b = pb[ROWF2];

    const int iters = (band_in + 7) & ~7;       // 80
    for (int ib = 0; ib < iters; ib += 8) {
#pragma unroll
        for (int p = 0; p < 8; ++p) {
            const int i = ib + p;
            if (i < band_in) {
                // ---- prefetch new row i+2 (immediate offset) ----
                float2 nx2a = make_float2(0.f, 0.f), nx2b = nx2a;
                if (i + 2 < band_in) {
                    nx2a = pa[(p + 2) * ROWF2]; nx2b = pb[(p + 2) * ROWF2];
                }
                // ---- re-load dropped row i-8 from cache (negative offset) ----
                float2 olda = make_float2(0.f, 0.f), oldb = olda;
                if (i >= 8) {
                    olda = pa[(p - 8) * ROWF2]; oldb = pb[(p - 8) * ROWF2];
                }

                // ---- update 4 column sums per col (add row i, drop i-8) ----
                const float a0 = cura.x, a1 = cura.y;
                const float b0 = curb.x, b1 = curb.y;

                S[0][0] += a0 - olda.x;           S[1][0] += a1 - olda.y;
                S[0][1] += b0 - oldb.x;           S[1][1] += b1 - oldb.y;
                S[0][2] = fmaf(a0, a0, fmaf(b0, b0,
                          fmaf(-olda.x, olda.x, fmaf(-oldb.x, oldb.x, S[0][2]))));
                S[1][2] = fmaf(a1, a1, fmaf(b1, b1,
                          fmaf(-olda.y, olda.y, fmaf(-oldb.y, oldb.y, S[1][2]))));
                S[0][3] = fmaf(a0, b0, fmaf(-olda.x, oldb.x, S[0][3]));
                S[1][3] = fmaf(a1, b1, fmaf(-olda.y, oldb.y, S[1][3]));

                // ---- horizontal window sums across lanes + SSIM ----
                if (i >= 7) {
                    float Ev[4], Od[4];
#pragma unroll
                    for (int q = 0; q < 4; ++q) {
                        const float s0 = S[0][q], s1 = S[1][q];
                        const float P = s0 + s1;
                        const float Q = P + __shfl_down_sync(FULLMASK, P, 1);
                        const float E = Q + __shfl_down_sync(FULLMASK, Q, 2);
                        const float O = (E - s0) + __shfl_down_sync(FULLMASK, s0, 4);
                        Ev[q] = E; Od[q] = O;
                    }
                    // even output (x = base + 2l)
                    const float m12e = Ev[0] * Ev[1];
                    const float mppe = fmaf(Ev[0], Ev[0], Ev[1] * Ev[1]);
                    const float sg12e = Ev[3] - m12e;
                    const float sgppe = Ev[2] - mppe;
                    const float nume = fmaf(2.f, m12e, C1f) * fmaf(2.f, sg12e, C2f);
                    const float dene = (mppe + C1f) * (sgppe + C2f);
                    // odd output (x = base + 2l + 1)
                    const float m12o = Od[0] * Od[1];
                    const float mppo = fmaf(Od[0], Od[0], Od[1] * Od[1]);
                    const float sg12o = Od[3] - m12o;
                    const float sgppo = Od[2] - mppo;
                    const float numo = fmaf(2.f, m12o, C1f) * fmaf(2.f, sg12o, C2f);
                    const float deno = (mppo + C1f) * (sgppo + C2f);
                    // combined single divide, masked lanes -> num 0 / den 1
                    const float ne = evenOK ? nume : 0.f;
                    const float de = evenOK ? dene : 1.f;
                    const float no = oddOK ? numo : 0.f;
                    const float dn = oddOK ? deno : 1.f;
                    const float t  = fmaf(ne, dn, no * de);
                    acc += cBase - __fdividef(t, de * dn);
                }
                cura = nx1a; curb = nx1b;
                nx1a = nx2a; nx1b = nx2b;
            }
        }
        pa += 8 * ROWF2; pb += 8 * ROWF2;
    }

    // ---- warp reduction, one double atomic per warp into per-image slot ----
#pragma unroll
    for (int o = 16; o; o >>= 1) acc += __shfl_xor_sync(FULLMASK, acc, o);
    if (l == 0) atomicAdd(&g_part[img], (double)acc);
}

extern "C" void kernel_launch(void* const* d_in, const int* in_sizes, int n_in,
                              void* d_out, int out_size)
{
    const float* A = (const float*)d_in[0];
    const float* B = (const float*)d_in[1];
    float* out = (float*)d_out;

    zero_acc_kernel<<<1, 128>>>();               // 1
    pad_kernel<<<1, 1>>>();                      // 2
    pad_kernel<<<1, 1>>>();                      // 3
    dim3 grid(NSTRIP, NB, NIMG / 2);             // 9 x 7 x 48 = 3024 CTAs (6048 warps, 1 wave)
    ssim_kernel<<<grid, 64>>>(A, B);             // 4  <- ncu capture position
    pad_kernel<<<1, 1>>>();                      // 5
    finalize_kernel<<<1, 32>>>(out);             // 6
}